// round 10
// baseline (speedup 1.0000x reference)
#include <cuda_runtime.h>
#include <cstdint>
#include <cstddef>

// ---------------- problem constants ----------------
#define FANOUT 10
#define N0_SZ 1362944
#define N1_SZ 123904
#define N2_SZ 11264
#define SEEDS_SZ 1024
#define IN_DIM 256
#define H_DIM 512
#define C_DIM 256

#define NUNITS (N1_SZ / 128)        // 968 layer-0 M-tiles
#define GATHER_CTAS 72
#define L1_UNITS (N2_SZ / 128)      // 88 layer-1 M-tiles
#define L1_GATHER_CTAS 64

// ---------------- device scratch (allocation-free rule) ----------------
__device__ __align__(16) float g_xr[(size_t)N1_SZ * IN_DIM];
__device__ __align__(16) float g_neigh0[(size_t)N1_SZ * IN_DIM];
__device__ __align__(16) float g_h1[(size_t)N1_SZ * H_DIM];
__device__ __align__(16) float g_neigh1[(size_t)N2_SZ * H_DIM];
__device__ __align__(16) float g_h2[(size_t)N2_SZ * H_DIM];
__device__ __align__(16) float g_neigh2[(size_t)SEEDS_SZ * H_DIM];
__device__ __align__(16) float g_Wt0s[(size_t)H_DIM * IN_DIM];
__device__ __align__(16) float g_Wt0n[(size_t)H_DIM * IN_DIM];
__device__ __align__(16) float g_Wt1s[(size_t)H_DIM * H_DIM];
__device__ __align__(16) float g_Wt1n[(size_t)H_DIM * H_DIM];
__device__ __align__(16) float g_Wt2s[(size_t)C_DIM * H_DIM];
__device__ __align__(16) float g_Wt2n[(size_t)C_DIM * H_DIM];
__device__ volatile unsigned g_ready0[NUNITS];
__device__ volatile unsigned g_ready1[L1_UNITS];

// ---------------- helpers (portable sm_80+ PTX) ----------------
__device__ __forceinline__ uint32_t smem_u32(const void* p) {
    uint32_t a;
    asm("{ .reg .u64 t; cvta.to.shared.u64 t, %1; cvt.u32.u64 %0, t; }" : "=r"(a) : "l"(p));
    return a;
}
__device__ __forceinline__ float cvt_tf32(float x) {
    float r; asm("cvt.rna.tf32.f32 %0, %1;" : "=f"(r) : "f"(x)); return r;
}
__device__ __forceinline__ void cp_async16(uint32_t dst, const void* src) {
    asm volatile("cp.async.cg.shared.global [%0], [%1], 16;" :: "r"(dst), "l"(src));
}
#define CP_COMMIT() asm volatile("cp.async.commit_group;" ::: "memory")
#define CP_WAIT(n)  asm volatile("cp.async.wait_group %0;" :: "n"(n) : "memory")

__device__ __forceinline__ void mma_tf32(float c[4],
                                         uint32_t a0, uint32_t a1, uint32_t a2, uint32_t a3,
                                         uint32_t b0, uint32_t b1) {
    asm volatile(
        "mma.sync.aligned.m16n8k8.row.col.f32.tf32.tf32.f32 "
        "{%0,%1,%2,%3}, {%4,%5,%6,%7}, {%8,%9}, {%0,%1,%2,%3};"
        : "+f"(c[0]), "+f"(c[1]), "+f"(c[2]), "+f"(c[3])
        : "r"(a0), "r"(a1), "r"(a2), "r"(a3), "r"(b0), "r"(b1));
}

__host__ __device__ __forceinline__ int perm8(int i) { return (i & 3) * 2 + (i >> 2); }

#define PADK 40
#define A_TILE_F (128 * PADK)               // 5120 floats
#define SMEM_GEMM_BYTES (4 * A_TILE_F * 4)  // layer0 / layer2 GEMM: 80KB
#define B1_TILE_F (64 * PADK)               // 2560 floats
#define STAGE1_F (A_TILE_F + B1_TILE_F)     // 7680 floats
#define SMEM_L1_BYTES (2 * STAGE1_F * 4)    // 60KB

// ---------------------------------------------------------------------------
// Layer-0 fused producer/consumer kernel.
// ---------------------------------------------------------------------------
__global__ __launch_bounds__(256, 2)
void layer0_fused_kernel(const float* __restrict__ x, const int* __restrict__ e0,
                         float* __restrict__ neigh0, float* __restrict__ xr,
                         const float* __restrict__ B0t, const float* __restrict__ B1t,
                         const float* __restrict__ bias, float* __restrict__ C) {
    extern __shared__ float sm[];
    const int tid = threadIdx.x;

    if (blockIdx.x < GATHER_CTAS) {
        const int t = tid & 31;
        const int ry = tid >> 5;
        const int dim8 = IN_DIM / 8;     // 32
        const float4* x4 = (const float4*)x;

        for (int u = blockIdx.x; u < NUNITS; u += GATHER_CTAS) {
            const int dbase = u * 128;
#pragma unroll 1
            for (int pass = 0; pass < 16; ++pass) {
                const int d = dbase + pass * 8 + ry;
                const int* s = e0 + (size_t)d * FANOUT;

                float4 a0 = make_float4(0.f, 0.f, 0.f, 0.f);
                float4 a1 = make_float4(0.f, 0.f, 0.f, 0.f);
#pragma unroll
                for (int e = 0; e < FANOUT; ++e) {
                    int r = __ldg(s + e);
                    const float4* p = x4 + ((size_t)r * dim8 + t) * 2;
                    float4 v0 = __ldg(p), v1 = __ldg(p + 1);
                    a0.x += v0.x; a0.y += v0.y; a0.z += v0.z; a0.w += v0.w;
                    a1.x += v1.x; a1.y += v1.y; a1.z += v1.z; a1.w += v1.w;
                }
                const float inv = 1.0f / FANOUT;
                a0.x = cvt_tf32(a0.x * inv); a0.y = cvt_tf32(a0.y * inv);
                a0.z = cvt_tf32(a0.z * inv); a0.w = cvt_tf32(a0.w * inv);
                a1.x = cvt_tf32(a1.x * inv); a1.y = cvt_tf32(a1.y * inv);
                a1.z = cvt_tf32(a1.z * inv); a1.w = cvt_tf32(a1.w * inv);

                float4* o = (float4*)neigh0 + ((size_t)d * dim8 + t) * 2;
                o[0] = make_float4(a0.x, a1.x, a0.y, a1.y);
                o[1] = make_float4(a0.z, a1.z, a0.w, a1.w);

                const float4* p = x4 + ((size_t)d * dim8 + t) * 2;
                float4 v0 = __ldg(p), v1 = __ldg(p + 1);
                v0.x = cvt_tf32(v0.x); v0.y = cvt_tf32(v0.y);
                v0.z = cvt_tf32(v0.z); v0.w = cvt_tf32(v0.w);
                v1.x = cvt_tf32(v1.x); v1.y = cvt_tf32(v1.y);
                v1.z = cvt_tf32(v1.z); v1.w = cvt_tf32(v1.w);
                float4* ox = (float4*)xr + ((size_t)d * dim8 + t) * 2;
                ox[0] = make_float4(v0.x, v1.x, v0.y, v1.y);
                ox[1] = make_float4(v0.z, v1.z, v0.w, v1.w);
            }
            __threadfence();
            __syncthreads();
            if (tid == 0) g_ready0[u] = 1;
        }
        return;
    }

    // GEMM consumer (K=256, N=512, BN=128)
    const int gbid = (int)blockIdx.x - GATHER_CTAS;
    const int n0 = (gbid & 3) * 128;
    const int mu = gbid >> 2;
    const int m0 = mu * 128;

    if (tid == 0) {
        while (g_ready0[mu] == 0) { __nanosleep(128); }
    }
    __syncthreads();

    const uint32_t sbase = smem_u32(sm);
    const int lane = tid & 31, w = tid >> 5;
    const int wm = w >> 2, wn = w & 3;
    const int K = IN_DIM, N = H_DIM;
    const int kc = K / 32, T = 2 * kc;

    float acc[4][4][4];
#pragma unroll
    for (int mi = 0; mi < 4; ++mi)
#pragma unroll
        for (int ni = 0; ni < 4; ++ni)
#pragma unroll
            for (int r = 0; r < 4; ++r) acc[mi][ni][r] = 0.f;

    const int srow = tid >> 3, sc4 = tid & 7;

    auto stage = [&](int chunk, int buf) {
        const int pair = (chunk >= kc) ? 1 : 0;
        const int k0 = (pair ? chunk - kc : chunk) * 32;
        const float* A = pair ? neigh0 : xr;
        const float* B = pair ? B1t : B0t;
        const uint32_t da = sbase + (uint32_t)buf * (A_TILE_F * 4);
        const uint32_t db = sbase + (uint32_t)(2 + buf) * (A_TILE_F * 4);
#pragma unroll
        for (int l = 0; l < 4; ++l) {
            int row = srow + l * 32;
            cp_async16(da + (uint32_t)(row * PADK + sc4 * 4) * 4,
                       A + (size_t)(m0 + row) * K + k0 + sc4 * 4);
        }
#pragma unroll
        for (int l = 0; l < 4; ++l) {
            int row = srow + l * 32;
            cp_async16(db + (uint32_t)(row * PADK + sc4 * 4) * 4,
                       B + (size_t)(n0 + row) * K + k0 + sc4 * 4);
        }
        CP_COMMIT();
    };

    stage(0, 0);
    int buf = 0;
    const int q2 = (lane & 3) * 2;
    const int rr = lane >> 2;

    for (int c = 0; c < T; ++c) {
        if (c + 1 < T) { stage(c + 1, buf ^ 1); CP_WAIT(1); }
        else           { CP_WAIT(0); }
        __syncthreads();

        const float* As = sm + buf * A_TILE_F;
        const float* Bs = sm + (2 + buf) * A_TILE_F;
#pragma unroll
        for (int ks = 0; ks < 4; ++ks) {
            uint32_t a[4][4], b[4][2];
            const int cc = ks * 8 + q2;
#pragma unroll
            for (int mi = 0; mi < 4; ++mi) {
                const float* p = As + (wm * 64 + mi * 16 + rr) * PADK + cc;
                float2 lo = *(const float2*)p;
                float2 hi = *(const float2*)(p + 8 * PADK);
                a[mi][0] = __float_as_uint(lo.x);
                a[mi][1] = __float_as_uint(hi.x);
                a[mi][2] = __float_as_uint(lo.y);
                a[mi][3] = __float_as_uint(hi.y);
            }
#pragma unroll
            for (int ni = 0; ni < 4; ++ni) {
                const float* p = Bs + (wn * 32 + ni * 8 + rr) * PADK + cc;
                float2 v = *(const float2*)p;
                b[ni][0] = __float_as_uint(v.x);
                b[ni][1] = __float_as_uint(v.y);
            }
#pragma unroll
            for (int mi = 0; mi < 4; ++mi)
#pragma unroll
                for (int ni = 0; ni < 4; ++ni)
                    mma_tf32(acc[mi][ni], a[mi][0], a[mi][1], a[mi][2], a[mi][3],
                             b[ni][0], b[ni][1]);
        }
        __syncthreads();
        buf ^= 1;
    }

#pragma unroll
    for (int ni = 0; ni < 4; ++ni) {
        const int n = n0 + wn * 32 + ni * 8 + 2 * (lane & 3);
        const float bx = __ldg(bias + n), by = __ldg(bias + n + 1);
#pragma unroll
        for (int mi = 0; mi < 4; ++mi) {
            const int m = m0 + wm * 64 + mi * 16 + (lane >> 2);
            float v00 = cvt_tf32(fmaxf(acc[mi][ni][0] + bx, 0.f));
            float v01 = cvt_tf32(fmaxf(acc[mi][ni][1] + by, 0.f));
            float v10 = cvt_tf32(fmaxf(acc[mi][ni][2] + bx, 0.f));
            float v11 = cvt_tf32(fmaxf(acc[mi][ni][3] + by, 0.f));
            const int g = n & ~7;
            const int p0 = g | perm8(n & 7), p1 = g | perm8((n + 1) & 7);
            C[(size_t)m * N + p0] = v00;
            C[(size_t)m * N + p1] = v01;
            C[(size_t)(m + 8) * N + p0] = v10;
            C[(size_t)(m + 8) * N + p1] = v11;
        }
    }
}

// ---------------------------------------------------------------------------
// Layer-1 fused producer/consumer kernel (BN=64 consumers, BK=32).
// FIX vs R9: B tile = 64 rows x 32 floats = 512 cp16 -> 2 per thread.
// ---------------------------------------------------------------------------
__global__ __launch_bounds__(256, 2)
void layer1_fused_kernel(const float* __restrict__ h1, const int* __restrict__ e1,
                         float* __restrict__ neigh1,
                         const float* __restrict__ B0t, const float* __restrict__ B1t,
                         const float* __restrict__ bias, float* __restrict__ C) {
    extern __shared__ float sm[];
    const int tid = threadIdx.x;

    if (blockIdx.x < L1_GATHER_CTAS) {
        const int t = tid & 31;
        const int ry = tid >> 5;
        const int dim8 = H_DIM / 8;      // 64
        const float4* h4 = (const float4*)h1;

        for (int u = blockIdx.x; u < L1_UNITS; u += L1_GATHER_CTAS) {
            const int dbase = u * 128;
#pragma unroll 1
            for (int pass = 0; pass < 16; ++pass) {
                const int d = dbase + pass * 8 + ry;
                const int* s = e1 + (size_t)d * FANOUT;
#pragma unroll
                for (int half = 0; half < 2; ++half) {
                    const int g = t + half * 32;
                    float4 a0 = make_float4(0.f, 0.f, 0.f, 0.f);
                    float4 a1 = make_float4(0.f, 0.f, 0.f, 0.f);
#pragma unroll
                    for (int e = 0; e < FANOUT; ++e) {
                        int r = __ldg(s + e);
                        const float4* p = h4 + ((size_t)r * dim8 + g) * 2;
                        float4 v0 = __ldg(p), v1 = __ldg(p + 1);
                        a0.x += v0.x; a0.y += v0.y; a0.z += v0.z; a0.w += v0.w;
                        a1.x += v1.x; a1.y += v1.y; a1.z += v1.z; a1.w += v1.w;
                    }
                    const float inv = 1.0f / FANOUT;
                    a0.x = cvt_tf32(a0.x * inv); a0.y = cvt_tf32(a0.y * inv);
                    a0.z = cvt_tf32(a0.z * inv); a0.w = cvt_tf32(a0.w * inv);
                    a1.x = cvt_tf32(a1.x * inv); a1.y = cvt_tf32(a1.y * inv);
                    a1.z = cvt_tf32(a1.z * inv); a1.w = cvt_tf32(a1.w * inv);
                    float4* o = (float4*)neigh1 + ((size_t)d * dim8 + g) * 2;
                    o[0] = a0;
                    o[1] = a1;
                }
            }
            __threadfence();
            __syncthreads();
            if (tid == 0) g_ready1[u] = 1;
        }
        return;
    }

    // GEMM consumer (K=512, N=512, BN=64)
    const int gbid = (int)blockIdx.x - L1_GATHER_CTAS;
    const int n0 = (gbid & 7) * 64;
    const int mu = gbid >> 3;
    const int m0 = mu * 128;

    const uint32_t sbase = smem_u32(sm);
    const int lane = tid & 31, w = tid >> 5;
    const int wm = w >> 2, wn = w & 3;
    const int K = H_DIM, N = H_DIM;
    const int kc = 16, T = 32;

    float acc[4][2][4];
#pragma unroll
    for (int mi = 0; mi < 4; ++mi)
#pragma unroll
        for (int ni = 0; ni < 2; ++ni)
#pragma unroll
            for (int r = 0; r < 4; ++r) acc[mi][ni][r] = 0.f;

    const int srow = tid >> 3, sc4 = tid & 7;

    auto stage = [&](int chunk, int buf) {
        const int pair = (chunk >= kc) ? 1 : 0;
        const int k0 = (pair ? chunk - kc : chunk) * 32;
        const float* A = pair ? neigh1 : h1;
        const float* B = pair ? B1t : B0t;
        const uint32_t da = sbase + (uint32_t)(buf * STAGE1_F) * 4;
        const uint32_t db = da + (uint32_t)A_TILE_F * 4;
#pragma unroll
        for (int l = 0; l < 4; ++l) {
            int row = srow + l * 32;
            cp_async16(da + (uint32_t)(row * PADK + sc4 * 4) * 4,
                       A + (size_t)(m0 + row) * K + k0 + sc4 * 4);
        }
        // B: 64 rows x 32 floats = 512 cp16 -> 2 per thread (FIXED)
#pragma unroll
        for (int l = 0; l < 2; ++l) {
            int i = tid + l * 256;
            int row = i >> 3, c4 = i & 7;
            cp_async16(db + (uint32_t)(row * PADK + c4 * 4) * 4,
                       B + (size_t)(n0 + row) * K + k0 + c4 * 4);
        }
        CP_COMMIT();
    };

    stage(0, 0);    // chunk 0 is h1: no wait needed
    int buf = 0;
    const int q2 = (lane & 3) * 2;
    const int rr = lane >> 2;

    for (int c = 0; c < T; ++c) {
        if (c + 1 < T) {
            if (c + 1 == kc) {   // first neigh1 chunk: wait for this m-tile
                if (tid == 0) {
                    while (g_ready1[mu] == 0) { __nanosleep(128); }
                }
                __syncthreads();
            }
            stage(c + 1, buf ^ 1);
            CP_WAIT(1);
        } else {
            CP_WAIT(0);
        }
        __syncthreads();

        const float* As = sm + buf * STAGE1_F;
        const float* Bs = As + A_TILE_F;
#pragma unroll
        for (int ks = 0; ks < 4; ++ks) {
            uint32_t a[4][4], b[2][2];
            const int cc = ks * 8 + q2;
#pragma unroll
            for (int mi = 0; mi < 4; ++mi) {
                const float* p = As + (wm * 64 + mi * 16 + rr) * PADK + cc;
                float2 lo = *(const float2*)p;
                float2 hi = *(const float2*)(p + 8 * PADK);
                a[mi][0] = __float_as_uint(lo.x);
                a[mi][1] = __float_as_uint(hi.x);
                a[mi][2] = __float_as_uint(lo.y);
                a[mi][3] = __float_as_uint(hi.y);
            }
#pragma unroll
            for (int ni = 0; ni < 2; ++ni) {
                const float* p = Bs + (wn * 16 + ni * 8 + rr) * PADK + cc;
                float2 v = *(const float2*)p;
                b[ni][0] = __float_as_uint(v.x);
                b[ni][1] = __float_as_uint(v.y);
            }
#pragma unroll
            for (int mi = 0; mi < 4; ++mi)
#pragma unroll
                for (int ni = 0; ni < 2; ++ni)
                    mma_tf32(acc[mi][ni], a[mi][0], a[mi][1], a[mi][2], a[mi][3],
                             b[ni][0], b[ni][1]);
        }
        __syncthreads();
        buf ^= 1;
    }

    // epilogue: bias + ReLU + tf32 round + permuted store (feeds layer 2)
#pragma unroll
    for (int ni = 0; ni < 2; ++ni) {
        const int n = n0 + wn * 16 + ni * 8 + 2 * (lane & 3);
        const float bx = __ldg(bias + n), by = __ldg(bias + n + 1);
#pragma unroll
        for (int mi = 0; mi < 4; ++mi) {
            const int m = m0 + wm * 64 + mi * 16 + (lane >> 2);
            float v00 = cvt_tf32(fmaxf(acc[mi][ni][0] + bx, 0.f));
            float v01 = cvt_tf32(fmaxf(acc[mi][ni][1] + by, 0.f));
            float v10 = cvt_tf32(fmaxf(acc[mi][ni][2] + bx, 0.f));
            float v11 = cvt_tf32(fmaxf(acc[mi][ni][3] + by, 0.f));
            const int g = n & ~7;
            const int p0 = g | perm8(n & 7), p1 = g | perm8((n + 1) & 7);
            C[(size_t)m * N + p0] = v00;
            C[(size_t)m * N + p1] = v01;
            C[(size_t)(m + 8) * N + p0] = v10;
            C[(size_t)(m + 8) * N + p1] = v11;
        }
    }
}

// ---------------------------------------------------------------------------
// gather-mean, layout-preserving (for gather2)
// ---------------------------------------------------------------------------
__global__ void gather_mean_kernel(const float* __restrict__ h,
                                   const int* __restrict__ src,
                                   float* __restrict__ out, int dim8, int num_dst) {
    const int d = blockIdx.x * blockDim.y + threadIdx.y;
    if (d >= num_dst) return;
    const int t = threadIdx.x;
    const int* s = src + (size_t)d * FANOUT;
    const float4* h4 = (const float4*)h;

    float4 a0 = make_float4(0.f, 0.f, 0.f, 0.f);
    float4 a1 = make_float4(0.f, 0.f, 0.f, 0.f);
#pragma unroll
    for (int e = 0; e < FANOUT; ++e) {
        int r = __ldg(s + e);
        const float4* p = h4 + ((size_t)r * dim8 + t) * 2;
        float4 v0 = __ldg(p), v1 = __ldg(p + 1);
        a0.x += v0.x; a0.y += v0.y; a0.z += v0.z; a0.w += v0.w;
        a1.x += v1.x; a1.y += v1.y; a1.z += v1.z; a1.w += v1.w;
    }
    const float inv = 1.0f / FANOUT;
    a0.x = cvt_tf32(a0.x * inv); a0.y = cvt_tf32(a0.y * inv);
    a0.z = cvt_tf32(a0.z * inv); a0.w = cvt_tf32(a0.w * inv);
    a1.x = cvt_tf32(a1.x * inv); a1.y = cvt_tf32(a1.y * inv);
    a1.z = cvt_tf32(a1.z * inv); a1.w = cvt_tf32(a1.w * inv);

    float4* o = (float4*)out + ((size_t)d * dim8 + t) * 2;
    o[0] = a0;
    o[1] = a1;
}

// ---------------------------------------------------------------------------
// Merged weight transpose (6 jobs) + flag clears, ONE launch.
// ---------------------------------------------------------------------------
__global__ void transpose_all_kernel(const float* W0, float* D0,
                                     const float* W1, float* D1,
                                     const float* W2, float* D2,
                                     const float* W3, float* D3,
                                     const float* W4, float* D4,
                                     const float* W5, float* D5) {
    const int b = blockIdx.x;
    const int tid = threadIdx.y * 32 + threadIdx.x;
    if (b == 0) {
        for (int i = tid; i < NUNITS; i += 256) g_ready0[i] = 0;
    } else if (b == 1) {
        for (int i = tid; i < L1_UNITS; i += 256) g_ready1[i] = 0;
    }
    const float* W; float* Wt; int K, N, t;
    if (b < 256) {
        K = IN_DIM; N = H_DIM;
        if (b < 128) { W = W0; Wt = D0; t = b; }
        else         { W = W1; Wt = D1; t = b - 128; }
    } else if (b < 768) {
        K = H_DIM; N = H_DIM;
        if (b < 512) { W = W2; Wt = D2; t = b - 256; }
        else         { W = W3; Wt = D3; t = b - 512; }
    } else {
        K = H_DIM; N = C_DIM;
        if (b < 896) { W = W4; Wt = D4; t = b - 768; }
        else         { W = W5; Wt = D5; t = b - 896; }
    }
    const int ntx = N / 32;
    const int bx = (t % ntx) * 32, by = (t / ntx) * 32;

    __shared__ float tile[32][33];
#pragma unroll
    for (int i = threadIdx.y; i < 32; i += 8)
        tile[i][threadIdx.x] = __ldg(W + (size_t)(by + i) * N + bx + threadIdx.x);
    __syncthreads();
#pragma unroll
    for (int i = threadIdx.y; i < 32; i += 8) {
        int k = by + threadIdx.x;
        int kp = (k & ~7) | perm8(k & 7);
        Wt[(size_t)(bx + i) * K + kp] = cvt_tf32(tile[threadIdx.x][i]);
    }
}

// ---------------------------------------------------------------------------
// tf32 mma.sync dual-GEMM (R3 config, BN=128) — layer 2 only.
// ---------------------------------------------------------------------------
template <bool INTERMEDIATE>
__global__ __launch_bounds__(256, 2)
void sage_mma_gemm(const float* __restrict__ A0, const float* __restrict__ A1,
                   const float* __restrict__ B0t, const float* __restrict__ B1t,
                   const float* __restrict__ bias, float* __restrict__ C,
                   int K, int N) {
    extern __shared__ float sm[];
    const uint32_t sbase = smem_u32(sm);
    const int tid = threadIdx.x, lane = tid & 31, w = tid >> 5;
    const int wm = w >> 2, wn = w & 3;
    const int m0 = blockIdx.y * 128, n0 = blockIdx.x * 128;
    const int kc = K / 32;
    const int T = 2 * kc;

    float acc[4][4][4];
#pragma unroll
    for (int mi = 0; mi < 4; ++mi)
#pragma unroll
        for (int ni = 0; ni < 4; ++ni)
#pragma unroll
            for (int r = 0; r < 4; ++r) acc[mi][ni][r] = 0.f;

    const int srow = tid >> 3, sc4 = tid & 7;

    auto stage = [&](int chunk, int buf) {
        const int pair = (chunk >= kc) ? 1 : 0;
        const int k0 = (pair ? chunk - kc : chunk) * 32;
        const float* A = pair ? A1 : A0;
        const float* B = pair ? B1t : B0t;
        const uint32_t da = sbase + (uint32_t)buf * (A_TILE_F * 4);
        const uint32_t db = sbase + (uint32_t)(2 + buf) * (A_TILE_F * 4);
#pragma unroll
        for (int l = 0; l < 4; ++l) {
            int row = srow + l * 32;
            cp_async16(da + (uint32_t)(row * PADK + sc4 * 4) * 4,
                       A + (size_t)(m0 + row) * K + k0 + sc4 * 4);
        }
#pragma unroll
        for (int l = 0; l < 4; ++l) {
            int row = srow + l * 32;
            cp_async16(db + (uint32_t)(row * PADK + sc4 * 4) * 4,
                       B + (size_t)(n0 + row) * K + k0 + sc4 * 4);
        }
        CP_COMMIT();
    };

    stage(0, 0);
    int buf = 0;
    const int q2 = (lane & 3) * 2;
    const int rr = lane >> 2;

    for (int c = 0; c < T; ++c) {
        if (c + 1 < T) { stage(c + 1, buf ^ 1); CP_WAIT(1); }
        else           { CP_WAIT(0); }
        __syncthreads();

        const float* As = sm + buf * A_TILE_F;
        const float* Bs = sm + (2 + buf) * A_TILE_F;
#pragma unroll
        for (int ks = 0; ks < 4; ++ks) {
            uint32_t a[4][4], b[4][2];
            const int cc = ks * 8 + q2;
#pragma unroll
            for (int mi = 0; mi < 4; ++mi) {
                const float* p = As + (wm * 64 + mi * 16 + rr) * PADK + cc;
                float2 lo = *(const float2*)p;
                float2 hi = *(const float2*)(p + 8 * PADK);
                a[mi][0] = __float_as_uint(lo.x);
                a[mi][1] = __float_as_uint(hi.x);
                a[mi][2] = __float_as_uint(lo.y);
                a[mi][3] = __float_as_uint(hi.y);
            }
#pragma unroll
            for (int ni = 0; ni < 4; ++ni) {
                const float* p = Bs + (wn * 32 + ni * 8 + rr) * PADK + cc;
                float2 v = *(const float2*)p;
                b[ni][0] = __float_as_uint(v.x);
                b[ni][1] = __float_as_uint(v.y);
            }
#pragma unroll
            for (int mi = 0; mi < 4; ++mi)
#pragma unroll
                for (int ni = 0; ni < 4; ++ni)
                    mma_tf32(acc[mi][ni], a[mi][0], a[mi][1], a[mi][2], a[mi][3],
                             b[ni][0], b[ni][1]);
        }
        __syncthreads();
        buf ^= 1;
    }

#pragma unroll
    for (int ni = 0; ni < 4; ++ni) {
        const int n = n0 + wn * 32 + ni * 8 + 2 * (lane & 3);
        const float bx = __ldg(bias + n), by = __ldg(bias + n + 1);
#pragma unroll
        for (int mi = 0; mi < 4; ++mi) {
            const int m = m0 + wm * 64 + mi * 16 + (lane >> 2);
            float v00 = acc[mi][ni][0] + bx, v01 = acc[mi][ni][1] + by;
            float v10 = acc[mi][ni][2] + bx, v11 = acc[mi][ni][3] + by;
            if (INTERMEDIATE) {
                v00 = cvt_tf32(fmaxf(v00, 0.f)); v01 = cvt_tf32(fmaxf(v01, 0.f));
                v10 = cvt_tf32(fmaxf(v10, 0.f)); v11 = cvt_tf32(fmaxf(v11, 0.f));
                const int g = n & ~7;
                const int p0 = g | perm8(n & 7), p1 = g | perm8((n + 1) & 7);
                C[(size_t)m * N + p0] = v00;
                C[(size_t)m * N + p1] = v01;
                C[(size_t)(m + 8) * N + p0] = v10;
                C[(size_t)(m + 8) * N + p1] = v11;
            } else {
                *(float2*)(C + (size_t)m * N + n) = make_float2(v00, v01);
                *(float2*)(C + (size_t)(m + 8) * N + n) = make_float2(v10, v11);
            }
        }
    }
}

// ---------------------------------------------------------------------------
extern "C" void kernel_launch(void* const* d_in, const int* in_sizes, int n_in,
                              void* d_out, int out_size) {
    const float* x   = (const float*)d_in[0];
    const float* Ws0 = (const float*)d_in[1];
    const float* Wn0 = (const float*)d_in[2];
    const float* b0  = (const float*)d_in[3];
    const float* Ws1 = (const float*)d_in[4];
    const float* Wn1 = (const float*)d_in[5];
    const float* b1  = (const float*)d_in[6];
    const float* Ws2 = (const float*)d_in[7];
    const float* Wn2 = (const float*)d_in[8];
    const float* b2  = (const float*)d_in[9];
    const int*   e0  = (const int*)d_in[10];
    const int*   e1  = (const int*)d_in[11];
    const int*   e2  = (const int*)d_in[12];
    float* out = (float*)d_out;

    float *xr, *neigh0, *h1, *neigh1, *h2, *neigh2;
    float *Wt0s, *Wt0n, *Wt1s, *Wt1n, *Wt2s, *Wt2n;
    cudaGetSymbolAddress((void**)&xr,     g_xr);
    cudaGetSymbolAddress((void**)&neigh0, g_neigh0);
    cudaGetSymbolAddress((void**)&h1,     g_h1);
    cudaGetSymbolAddress((void**)&neigh1, g_neigh1);
    cudaGetSymbolAddress((void**)&h2,     g_h2);
    cudaGetSymbolAddress((void**)&neigh2, g_neigh2);
    cudaGetSymbolAddress((void**)&Wt0s,   g_Wt0s);
    cudaGetSymbolAddress((void**)&Wt0n,   g_Wt0n);
    cudaGetSymbolAddress((void**)&Wt1s,   g_Wt1s);
    cudaGetSymbolAddress((void**)&Wt1n,   g_Wt1n);
    cudaGetSymbolAddress((void**)&Wt2s,   g_Wt2s);
    cudaGetSymbolAddress((void**)&Wt2n,   g_Wt2n);

    cudaFuncSetAttribute((const void*)layer0_fused_kernel,
                         cudaFuncAttributeMaxDynamicSharedMemorySize, SMEM_GEMM_BYTES);
    cudaFuncSetAttribute((const void*)layer1_fused_kernel,
                         cudaFuncAttributeMaxDynamicSharedMemorySize, SMEM_L1_BYTES);
    cudaFuncSetAttribute((const void*)sage_mma_gemm<false>,
                         cudaFuncAttributeMaxDynamicSharedMemorySize, SMEM_GEMM_BYTES);

    // #1: transposes + flag clears
    transpose_all_kernel<<<1024, dim3(32, 8)>>>(Ws0, Wt0s, Wn0, Wt0n,
                                                Ws1, Wt1s, Wn1, Wt1n,
                                                Ws2, Wt2s, Wn2, Wt2n);
    // #2: fused layer 0 (72 gather producers + 3872 GEMM consumers)
    layer0_fused_kernel<<<GATHER_CTAS + 4 * NUNITS, 256, SMEM_GEMM_BYTES>>>(
        x, e0, neigh0, xr, Wt0s, Wt0n, b0, h1);
    // #3: fused layer 1 (64 gather producers + 704 BN=64 GEMM consumers)
    layer1_fused_kernel<<<L1_GATHER_CTAS + 8 * L1_UNITS, 256, SMEM_L1_BYTES>>>(
        h1, e1, neigh1, Wt1s, Wt1n, b1, h2);
    // #4: gather2
    gather_mean_kernel<<<SEEDS_SZ / 4, dim3(H_DIM / 8, 4)>>>(h2, e2, neigh2, H_DIM / 8, SEEDS_SZ);
    // #5: Layer-2 dual GEMM (canonical output layout)
    sage_mma_gemm<false><<<dim3(C_DIM / 128, SEEDS_SZ / 128), 256, SMEM_GEMM_BYTES>>>(
        h2, neigh2, Wt2s, Wt2n, b2, out, H_DIM, C_DIM);
}

// round 11
// speedup vs baseline: 1.0406x; 1.0406x over previous
#include <cuda_runtime.h>
#include <cstdint>
#include <cstddef>

// ---------------- problem constants ----------------
#define FANOUT 10
#define N0_SZ 1362944
#define N1_SZ 123904
#define N2_SZ 11264
#define SEEDS_SZ 1024
#define IN_DIM 256
#define H_DIM 512
#define C_DIM 256

#define NUNITS (N1_SZ / 128)        // 968 layer-0 M-tiles
#define GATHER_CTAS 104

// ---------------- device scratch (allocation-free rule) ----------------
__device__ __align__(16) float g_xr[(size_t)N1_SZ * IN_DIM];
__device__ __align__(16) float g_neigh0[(size_t)N1_SZ * IN_DIM];
__device__ __align__(16) float g_h1[(size_t)N1_SZ * H_DIM];
__device__ __align__(16) float g_neigh1[(size_t)N2_SZ * H_DIM];
__device__ __align__(16) float g_h2[(size_t)N2_SZ * H_DIM];
__device__ __align__(16) float g_neigh2[(size_t)SEEDS_SZ * H_DIM];
__device__ __align__(16) float g_Wt0s[(size_t)H_DIM * IN_DIM];
__device__ __align__(16) float g_Wt0n[(size_t)H_DIM * IN_DIM];
__device__ __align__(16) float g_Wt1s[(size_t)H_DIM * H_DIM];
__device__ __align__(16) float g_Wt1n[(size_t)H_DIM * H_DIM];
__device__ __align__(16) float g_Wt2s[(size_t)C_DIM * H_DIM];
__device__ __align__(16) float g_Wt2n[(size_t)C_DIM * H_DIM];
__device__ volatile unsigned g_ready0[NUNITS];

// ---------------- helpers (portable sm_80+ PTX) ----------------
__device__ __forceinline__ uint32_t smem_u32(const void* p) {
    uint32_t a;
    asm("{ .reg .u64 t; cvta.to.shared.u64 t, %1; cvt.u32.u64 %0, t; }" : "=r"(a) : "l"(p));
    return a;
}
__device__ __forceinline__ float cvt_tf32(float x) {
    float r; asm("cvt.rna.tf32.f32 %0, %1;" : "=f"(r) : "f"(x)); return r;
}
__device__ __forceinline__ void cp_async16(uint32_t dst, const void* src) {
    asm volatile("cp.async.cg.shared.global [%0], [%1], 16;" :: "r"(dst), "l"(src));
}
#define CP_COMMIT() asm volatile("cp.async.commit_group;" ::: "memory")
#define CP_WAIT(n)  asm volatile("cp.async.wait_group %0;" :: "n"(n) : "memory")

__device__ __forceinline__ void mma_tf32(float c[4],
                                         uint32_t a0, uint32_t a1, uint32_t a2, uint32_t a3,
                                         uint32_t b0, uint32_t b1) {
    asm volatile(
        "mma.sync.aligned.m16n8k8.row.col.f32.tf32.tf32.f32 "
        "{%0,%1,%2,%3}, {%4,%5,%6,%7}, {%8,%9}, {%0,%1,%2,%3};"
        : "+f"(c[0]), "+f"(c[1]), "+f"(c[2]), "+f"(c[3])
        : "r"(a0), "r"(a1), "r"(a2), "r"(a3), "r"(b0), "r"(b1));
}

__host__ __device__ __forceinline__ int perm8(int i) { return (i & 3) * 2 + (i >> 2); }

#define PADK 40
#define A_TILE_F (128 * PADK)               // 5120 floats
#define SMEM_GEMM_BYTES (4 * A_TILE_F * 4)  // BN=128 GEMM: 80KB
#define B64_TILE_F (64 * PADK)              // 2560 floats
#define STAGE64_F (A_TILE_F + B64_TILE_F)   // 7680 floats
#define SMEM_B64_BYTES (2 * STAGE64_F * 4)  // 60KB

// ---------------------------------------------------------------------------
// Layer-0 fused producer/consumer kernel (R8 structure, 104 producers).
// ---------------------------------------------------------------------------
__global__ __launch_bounds__(256, 2)
void layer0_fused_kernel(const float* __restrict__ x, const int* __restrict__ e0,
                         float* __restrict__ neigh0, float* __restrict__ xr,
                         const float* __restrict__ B0t, const float* __restrict__ B1t,
                         const float* __restrict__ bias, float* __restrict__ C) {
    extern __shared__ float sm[];
    const int tid = threadIdx.x;

    if (blockIdx.x < GATHER_CTAS) {
        const int t = tid & 31;
        const int ry = tid >> 5;
        const int dim8 = IN_DIM / 8;     // 32
        const float4* x4 = (const float4*)x;

        for (int u = blockIdx.x; u < NUNITS; u += GATHER_CTAS) {
            const int dbase = u * 128;
#pragma unroll 1
            for (int pass = 0; pass < 16; ++pass) {
                const int d = dbase + pass * 8 + ry;
                const int* s = e0 + (size_t)d * FANOUT;

                float4 a0 = make_float4(0.f, 0.f, 0.f, 0.f);
                float4 a1 = make_float4(0.f, 0.f, 0.f, 0.f);
#pragma unroll
                for (int e = 0; e < FANOUT; ++e) {
                    int r = __ldg(s + e);
                    const float4* p = x4 + ((size_t)r * dim8 + t) * 2;
                    float4 v0 = __ldg(p), v1 = __ldg(p + 1);
                    a0.x += v0.x; a0.y += v0.y; a0.z += v0.z; a0.w += v0.w;
                    a1.x += v1.x; a1.y += v1.y; a1.z += v1.z; a1.w += v1.w;
                }
                const float inv = 1.0f / FANOUT;
                a0.x = cvt_tf32(a0.x * inv); a0.y = cvt_tf32(a0.y * inv);
                a0.z = cvt_tf32(a0.z * inv); a0.w = cvt_tf32(a0.w * inv);
                a1.x = cvt_tf32(a1.x * inv); a1.y = cvt_tf32(a1.y * inv);
                a1.z = cvt_tf32(a1.z * inv); a1.w = cvt_tf32(a1.w * inv);

                float4* o = (float4*)neigh0 + ((size_t)d * dim8 + t) * 2;
                o[0] = make_float4(a0.x, a1.x, a0.y, a1.y);
                o[1] = make_float4(a0.z, a1.z, a0.w, a1.w);

                const float4* p = x4 + ((size_t)d * dim8 + t) * 2;
                float4 v0 = __ldg(p), v1 = __ldg(p + 1);
                v0.x = cvt_tf32(v0.x); v0.y = cvt_tf32(v0.y);
                v0.z = cvt_tf32(v0.z); v0.w = cvt_tf32(v0.w);
                v1.x = cvt_tf32(v1.x); v1.y = cvt_tf32(v1.y);
                v1.z = cvt_tf32(v1.z); v1.w = cvt_tf32(v1.w);
                float4* ox = (float4*)xr + ((size_t)d * dim8 + t) * 2;
                ox[0] = make_float4(v0.x, v1.x, v0.y, v1.y);
                ox[1] = make_float4(v0.z, v1.z, v0.w, v1.w);
            }
            __threadfence();
            __syncthreads();
            if (tid == 0) g_ready0[u] = 1;
        }
        return;
    }

    // GEMM consumer (K=256, N=512, BN=128)
    const int gbid = (int)blockIdx.x - GATHER_CTAS;
    const int n0 = (gbid & 3) * 128;
    const int mu = gbid >> 2;
    const int m0 = mu * 128;

    if (tid == 0) {
        while (g_ready0[mu] == 0) { __nanosleep(128); }
    }
    __syncthreads();

    const uint32_t sbase = smem_u32(sm);
    const int lane = tid & 31, w = tid >> 5;
    const int wm = w >> 2, wn = w & 3;
    const int K = IN_DIM, N = H_DIM;
    const int kc = K / 32, T = 2 * kc;

    float acc[4][4][4];
#pragma unroll
    for (int mi = 0; mi < 4; ++mi)
#pragma unroll
        for (int ni = 0; ni < 4; ++ni)
#pragma unroll
            for (int r = 0; r < 4; ++r) acc[mi][ni][r] = 0.f;

    const int srow = tid >> 3, sc4 = tid & 7;

    auto stage = [&](int chunk, int buf) {
        const int pair = (chunk >= kc) ? 1 : 0;
        const int k0 = (pair ? chunk - kc : chunk) * 32;
        const float* A = pair ? neigh0 : xr;
        const float* B = pair ? B1t : B0t;
        const uint32_t da = sbase + (uint32_t)buf * (A_TILE_F * 4);
        const uint32_t db = sbase + (uint32_t)(2 + buf) * (A_TILE_F * 4);
#pragma unroll
        for (int l = 0; l < 4; ++l) {
            int row = srow + l * 32;
            cp_async16(da + (uint32_t)(row * PADK + sc4 * 4) * 4,
                       A + (size_t)(m0 + row) * K + k0 + sc4 * 4);
        }
#pragma unroll
        for (int l = 0; l < 4; ++l) {
            int row = srow + l * 32;
            cp_async16(db + (uint32_t)(row * PADK + sc4 * 4) * 4,
                       B + (size_t)(n0 + row) * K + k0 + sc4 * 4);
        }
        CP_COMMIT();
    };

    stage(0, 0);
    int buf = 0;
    const int q2 = (lane & 3) * 2;
    const int rr = lane >> 2;

    for (int c = 0; c < T; ++c) {
        if (c + 1 < T) { stage(c + 1, buf ^ 1); CP_WAIT(1); }
        else           { CP_WAIT(0); }
        __syncthreads();

        const float* As = sm + buf * A_TILE_F;
        const float* Bs = sm + (2 + buf) * A_TILE_F;
#pragma unroll
        for (int ks = 0; ks < 4; ++ks) {
            uint32_t a[4][4], b[4][2];
            const int cc = ks * 8 + q2;
#pragma unroll
            for (int mi = 0; mi < 4; ++mi) {
                const float* p = As + (wm * 64 + mi * 16 + rr) * PADK + cc;
                float2 lo = *(const float2*)p;
                float2 hi = *(const float2*)(p + 8 * PADK);
                a[mi][0] = __float_as_uint(lo.x);
                a[mi][1] = __float_as_uint(hi.x);
                a[mi][2] = __float_as_uint(lo.y);
                a[mi][3] = __float_as_uint(hi.y);
            }
#pragma unroll
            for (int ni = 0; ni < 4; ++ni) {
                const float* p = Bs + (wn * 32 + ni * 8 + rr) * PADK + cc;
                float2 v = *(const float2*)p;
                b[ni][0] = __float_as_uint(v.x);
                b[ni][1] = __float_as_uint(v.y);
            }
#pragma unroll
            for (int mi = 0; mi < 4; ++mi)
#pragma unroll
                for (int ni = 0; ni < 4; ++ni)
                    mma_tf32(acc[mi][ni], a[mi][0], a[mi][1], a[mi][2], a[mi][3],
                             b[ni][0], b[ni][1]);
        }
        __syncthreads();
        buf ^= 1;
    }

#pragma unroll
    for (int ni = 0; ni < 4; ++ni) {
        const int n = n0 + wn * 32 + ni * 8 + 2 * (lane & 3);
        const float bx = __ldg(bias + n), by = __ldg(bias + n + 1);
#pragma unroll
        for (int mi = 0; mi < 4; ++mi) {
            const int m = m0 + wm * 64 + mi * 16 + (lane >> 2);
            float v00 = cvt_tf32(fmaxf(acc[mi][ni][0] + bx, 0.f));
            float v01 = cvt_tf32(fmaxf(acc[mi][ni][1] + by, 0.f));
            float v10 = cvt_tf32(fmaxf(acc[mi][ni][2] + bx, 0.f));
            float v11 = cvt_tf32(fmaxf(acc[mi][ni][3] + by, 0.f));
            const int g = n & ~7;
            const int p0 = g | perm8(n & 7), p1 = g | perm8((n + 1) & 7);
            C[(size_t)m * N + p0] = v00;
            C[(size_t)m * N + p1] = v01;
            C[(size_t)(m + 8) * N + p0] = v10;
            C[(size_t)(m + 8) * N + p1] = v11;
        }
    }
}

// ---------------------------------------------------------------------------
// gather-mean, layout-preserving (gather1, gather2) — whole-chip
// ---------------------------------------------------------------------------
__global__ void gather_mean_kernel(const float* __restrict__ h,
                                   const int* __restrict__ src,
                                   float* __restrict__ out, int dim8, int num_dst) {
    const int d = blockIdx.x * blockDim.y + threadIdx.y;
    if (d >= num_dst) return;
    const int t = threadIdx.x;
    const int* s = src + (size_t)d * FANOUT;
    const float4* h4 = (const float4*)h;

    float4 a0 = make_float4(0.f, 0.f, 0.f, 0.f);
    float4 a1 = make_float4(0.f, 0.f, 0.f, 0.f);
#pragma unroll
    for (int e = 0; e < FANOUT; ++e) {
        int r = __ldg(s + e);
        const float4* p = h4 + ((size_t)r * dim8 + t) * 2;
        float4 v0 = __ldg(p), v1 = __ldg(p + 1);
        a0.x += v0.x; a0.y += v0.y; a0.z += v0.z; a0.w += v0.w;
        a1.x += v1.x; a1.y += v1.y; a1.z += v1.z; a1.w += v1.w;
    }
    const float inv = 1.0f / FANOUT;
    a0.x = cvt_tf32(a0.x * inv); a0.y = cvt_tf32(a0.y * inv);
    a0.z = cvt_tf32(a0.z * inv); a0.w = cvt_tf32(a0.w * inv);
    a1.x = cvt_tf32(a1.x * inv); a1.y = cvt_tf32(a1.y * inv);
    a1.z = cvt_tf32(a1.z * inv); a1.w = cvt_tf32(a1.w * inv);

    float4* o = (float4*)out + ((size_t)d * dim8 + t) * 2;
    o[0] = a0;
    o[1] = a1;
}

// ---------------------------------------------------------------------------
// Merged weight transpose (6 jobs) + flag clear, ONE launch.
// ---------------------------------------------------------------------------
__global__ void transpose_all_kernel(const float* W0, float* D0,
                                     const float* W1, float* D1,
                                     const float* W2, float* D2,
                                     const float* W3, float* D3,
                                     const float* W4, float* D4,
                                     const float* W5, float* D5) {
    const int b = blockIdx.x;
    const int tid = threadIdx.y * 32 + threadIdx.x;
    if (b == 0) {
        for (int i = tid; i < NUNITS; i += 256) g_ready0[i] = 0;
    }
    const float* W; float* Wt; int K, N, t;
    if (b < 256) {
        K = IN_DIM; N = H_DIM;
        if (b < 128) { W = W0; Wt = D0; t = b; }
        else         { W = W1; Wt = D1; t = b - 128; }
    } else if (b < 768) {
        K = H_DIM; N = H_DIM;
        if (b < 512) { W = W2; Wt = D2; t = b - 256; }
        else         { W = W3; Wt = D3; t = b - 512; }
    } else {
        K = H_DIM; N = C_DIM;
        if (b < 896) { W = W4; Wt = D4; t = b - 768; }
        else         { W = W5; Wt = D5; t = b - 896; }
    }
    const int ntx = N / 32;
    const int bx = (t % ntx) * 32, by = (t / ntx) * 32;

    __shared__ float tile[32][33];
#pragma unroll
    for (int i = threadIdx.y; i < 32; i += 8)
        tile[i][threadIdx.x] = __ldg(W + (size_t)(by + i) * N + bx + threadIdx.x);
    __syncthreads();
#pragma unroll
    for (int i = threadIdx.y; i < 32; i += 8) {
        int k = by + threadIdx.x;
        int kp = (k & ~7) | perm8(k & 7);
        Wt[(size_t)(bx + i) * K + kp] = cvt_tf32(tile[threadIdx.x][i]);
    }
}

// ---------------------------------------------------------------------------
// tf32 mma.sync dual-GEMM, BN=64 (better tail for M=11264 layer) — gemm1.
// ---------------------------------------------------------------------------
template <bool INTERMEDIATE>
__global__ __launch_bounds__(256, 2)
void sage_mma_gemm_bn64(const float* __restrict__ A0, const float* __restrict__ A1,
                        const float* __restrict__ B0t, const float* __restrict__ B1t,
                        const float* __restrict__ bias, float* __restrict__ C,
                        int K, int N) {
    extern __shared__ float sm[];
    const uint32_t sbase = smem_u32(sm);
    const int tid = threadIdx.x, lane = tid & 31, w = tid >> 5;
    const int wm = w >> 2, wn = w & 3;
    const int m0 = blockIdx.y * 128, n0 = blockIdx.x * 64;
    const int kc = K / 32, T = 2 * kc;

    float acc[4][2][4];
#pragma unroll
    for (int mi = 0; mi < 4; ++mi)
#pragma unroll
        for (int ni = 0; ni < 2; ++ni)
#pragma unroll
            for (int r = 0; r < 4; ++r) acc[mi][ni][r] = 0.f;

    const int srow = tid >> 3, sc4 = tid & 7;

    auto stage = [&](int chunk, int buf) {
        const int pair = (chunk >= kc) ? 1 : 0;
        const int k0 = (pair ? chunk - kc : chunk) * 32;
        const float* A = pair ? A1 : A0;
        const float* B = pair ? B1t : B0t;
        const uint32_t da = sbase + (uint32_t)(buf * STAGE64_F) * 4;
        const uint32_t db = da + (uint32_t)A_TILE_F * 4;
#pragma unroll
        for (int l = 0; l < 4; ++l) {
            int row = srow + l * 32;
            cp_async16(da + (uint32_t)(row * PADK + sc4 * 4) * 4,
                       A + (size_t)(m0 + row) * K + k0 + sc4 * 4);
        }
        // B: 64 rows x 32 floats = 512 cp16 -> 2 per thread
#pragma unroll
        for (int l = 0; l < 2; ++l) {
            int i = tid + l * 256;
            int row = i >> 3, c4 = i & 7;
            cp_async16(db + (uint32_t)(row * PADK + c4 * 4) * 4,
                       B + (size_t)(n0 + row) * K + k0 + c4 * 4);
        }
        CP_COMMIT();
    };

    stage(0, 0);
    int buf = 0;
    const int q2 = (lane & 3) * 2;
    const int rr = lane >> 2;

    for (int c = 0; c < T; ++c) {
        if (c + 1 < T) { stage(c + 1, buf ^ 1); CP_WAIT(1); }
        else           { CP_WAIT(0); }
        __syncthreads();

        const float* As = sm + buf * STAGE64_F;
        const float* Bs = As + A_TILE_F;
#pragma unroll
        for (int ks = 0; ks < 4; ++ks) {
            uint32_t a[4][4], b[2][2];
            const int cc = ks * 8 + q2;
#pragma unroll
            for (int mi = 0; mi < 4; ++mi) {
                const float* p = As + (wm * 64 + mi * 16 + rr) * PADK + cc;
                float2 lo = *(const float2*)p;
                float2 hi = *(const float2*)(p + 8 * PADK);
                a[mi][0] = __float_as_uint(lo.x);
                a[mi][1] = __float_as_uint(hi.x);
                a[mi][2] = __float_as_uint(lo.y);
                a[mi][3] = __float_as_uint(hi.y);
            }
#pragma unroll
            for (int ni = 0; ni < 2; ++ni) {
                const float* p = Bs + (wn * 16 + ni * 8 + rr) * PADK + cc;
                float2 v = *(const float2*)p;
                b[ni][0] = __float_as_uint(v.x);
                b[ni][1] = __float_as_uint(v.y);
            }
#pragma unroll
            for (int mi = 0; mi < 4; ++mi)
#pragma unroll
                for (int ni = 0; ni < 2; ++ni)
                    mma_tf32(acc[mi][ni], a[mi][0], a[mi][1], a[mi][2], a[mi][3],
                             b[ni][0], b[ni][1]);
        }
        __syncthreads();
        buf ^= 1;
    }

#pragma unroll
    for (int ni = 0; ni < 2; ++ni) {
        const int n = n0 + wn * 16 + ni * 8 + 2 * (lane & 3);
        const float bx = __ldg(bias + n), by = __ldg(bias + n + 1);
#pragma unroll
        for (int mi = 0; mi < 4; ++mi) {
            const int m = m0 + wm * 64 + mi * 16 + (lane >> 2);
            float v00 = acc[mi][ni][0] + bx, v01 = acc[mi][ni][1] + by;
            float v10 = acc[mi][ni][2] + bx, v11 = acc[mi][ni][3] + by;
            if (INTERMEDIATE) {
                v00 = cvt_tf32(fmaxf(v00, 0.f)); v01 = cvt_tf32(fmaxf(v01, 0.f));
                v10 = cvt_tf32(fmaxf(v10, 0.f)); v11 = cvt_tf32(fmaxf(v11, 0.f));
                const int g = n & ~7;
                const int p0 = g | perm8(n & 7), p1 = g | perm8((n + 1) & 7);
                C[(size_t)m * N + p0] = v00;
                C[(size_t)m * N + p1] = v01;
                C[(size_t)(m + 8) * N + p0] = v10;
                C[(size_t)(m + 8) * N + p1] = v11;
            } else {
                *(float2*)(C + (size_t)m * N + n) = make_float2(v00, v01);
                *(float2*)(C + (size_t)(m + 8) * N + n) = make_float2(v10, v11);
            }
        }
    }
}

// ---------------------------------------------------------------------------
// tf32 mma.sync dual-GEMM (BN=128, R3 config) — gemm2.
// ---------------------------------------------------------------------------
template <bool INTERMEDIATE>
__global__ __launch_bounds__(256, 2)
void sage_mma_gemm(const float* __restrict__ A0, const float* __restrict__ A1,
                   const float* __restrict__ B0t, const float* __restrict__ B1t,
                   const float* __restrict__ bias, float* __restrict__ C,
                   int K, int N) {
    extern __shared__ float sm[];
    const uint32_t sbase = smem_u32(sm);
    const int tid = threadIdx.x, lane = tid & 31, w = tid >> 5;
    const int wm = w >> 2, wn = w & 3;
    const int m0 = blockIdx.y * 128, n0 = blockIdx.x * 128;
    const int kc = K / 32;
    const int T = 2 * kc;

    float acc[4][4][4];
#pragma unroll
    for (int mi = 0; mi < 4; ++mi)
#pragma unroll
        for (int ni = 0; ni < 4; ++ni)
#pragma unroll
            for (int r = 0; r < 4; ++r) acc[mi][ni][r] = 0.f;

    const int srow = tid >> 3, sc4 = tid & 7;

    auto stage = [&](int chunk, int buf) {
        const int pair = (chunk >= kc) ? 1 : 0;
        const int k0 = (pair ? chunk - kc : chunk) * 32;
        const float* A = pair ? A1 : A0;
        const float* B = pair ? B1t : B0t;
        const uint32_t da = sbase + (uint32_t)buf * (A_TILE_F * 4);
        const uint32_t db = sbase + (uint32_t)(2 + buf) * (A_TILE_F * 4);
#pragma unroll
        for (int l = 0; l < 4; ++l) {
            int row = srow + l * 32;
            cp_async16(da + (uint32_t)(row * PADK + sc4 * 4) * 4,
                       A + (size_t)(m0 + row) * K + k0 + sc4 * 4);
        }
#pragma unroll
        for (int l = 0; l < 4; ++l) {
            int row = srow + l * 32;
            cp_async16(db + (uint32_t)(row * PADK + sc4 * 4) * 4,
                       B + (size_t)(n0 + row) * K + k0 + sc4 * 4);
        }
        CP_COMMIT();
    };

    stage(0, 0);
    int buf = 0;
    const int q2 = (lane & 3) * 2;
    const int rr = lane >> 2;

    for (int c = 0; c < T; ++c) {
        if (c + 1 < T) { stage(c + 1, buf ^ 1); CP_WAIT(1); }
        else           { CP_WAIT(0); }
        __syncthreads();

        const float* As = sm + buf * A_TILE_F;
        const float* Bs = sm + (2 + buf) * A_TILE_F;
#pragma unroll
        for (int ks = 0; ks < 4; ++ks) {
            uint32_t a[4][4], b[4][2];
            const int cc = ks * 8 + q2;
#pragma unroll
            for (int mi = 0; mi < 4; ++mi) {
                const float* p = As + (wm * 64 + mi * 16 + rr) * PADK + cc;
                float2 lo = *(const float2*)p;
                float2 hi = *(const float2*)(p + 8 * PADK);
                a[mi][0] = __float_as_uint(lo.x);
                a[mi][1] = __float_as_uint(hi.x);
                a[mi][2] = __float_as_uint(lo.y);
                a[mi][3] = __float_as_uint(hi.y);
            }
#pragma unroll
            for (int ni = 0; ni < 4; ++ni) {
                const float* p = Bs + (wn * 32 + ni * 8 + rr) * PADK + cc;
                float2 v = *(const float2*)p;
                b[ni][0] = __float_as_uint(v.x);
                b[ni][1] = __float_as_uint(v.y);
            }
#pragma unroll
            for (int mi = 0; mi < 4; ++mi)
#pragma unroll
                for (int ni = 0; ni < 4; ++ni)
                    mma_tf32(acc[mi][ni], a[mi][0], a[mi][1], a[mi][2], a[mi][3],
                             b[ni][0], b[ni][1]);
        }
        __syncthreads();
        buf ^= 1;
    }

#pragma unroll
    for (int ni = 0; ni < 4; ++ni) {
        const int n = n0 + wn * 32 + ni * 8 + 2 * (lane & 3);
        const float bx = __ldg(bias + n), by = __ldg(bias + n + 1);
#pragma unroll
        for (int mi = 0; mi < 4; ++mi) {
            const int m = m0 + wm * 64 + mi * 16 + (lane >> 2);
            float v00 = acc[mi][ni][0] + bx, v01 = acc[mi][ni][1] + by;
            float v10 = acc[mi][ni][2] + bx, v11 = acc[mi][ni][3] + by;
            if (INTERMEDIATE) {
                v00 = cvt_tf32(fmaxf(v00, 0.f)); v01 = cvt_tf32(fmaxf(v01, 0.f));
                v10 = cvt_tf32(fmaxf(v10, 0.f)); v11 = cvt_tf32(fmaxf(v11, 0.f));
                const int g = n & ~7;
                const int p0 = g | perm8(n & 7), p1 = g | perm8((n + 1) & 7);
                C[(size_t)m * N + p0] = v00;
                C[(size_t)m * N + p1] = v01;
                C[(size_t)(m + 8) * N + p0] = v10;
                C[(size_t)(m + 8) * N + p1] = v11;
            } else {
                *(float2*)(C + (size_t)m * N + n) = make_float2(v00, v01);
                *(float2*)(C + (size_t)(m + 8) * N + n) = make_float2(v10, v11);
            }
        }
    }
}

// ---------------------------------------------------------------------------
extern "C" void kernel_launch(void* const* d_in, const int* in_sizes, int n_in,
                              void* d_out, int out_size) {
    const float* x   = (const float*)d_in[0];
    const float* Ws0 = (const float*)d_in[1];
    const float* Wn0 = (const float*)d_in[2];
    const float* b0  = (const float*)d_in[3];
    const float* Ws1 = (const float*)d_in[4];
    const float* Wn1 = (const float*)d_in[5];
    const float* b1  = (const float*)d_in[6];
    const float* Ws2 = (const float*)d_in[7];
    const float* Wn2 = (const float*)d_in[8];
    const float* b2  = (const float*)d_in[9];
    const int*   e0  = (const int*)d_in[10];
    const int*   e1  = (const int*)d_in[11];
    const int*   e2  = (const int*)d_in[12];
    float* out = (float*)d_out;

    float *xr, *neigh0, *h1, *neigh1, *h2, *neigh2;
    float *Wt0s, *Wt0n, *Wt1s, *Wt1n, *Wt2s, *Wt2n;
    cudaGetSymbolAddress((void**)&xr,     g_xr);
    cudaGetSymbolAddress((void**)&neigh0, g_neigh0);
    cudaGetSymbolAddress((void**)&h1,     g_h1);
    cudaGetSymbolAddress((void**)&neigh1, g_neigh1);
    cudaGetSymbolAddress((void**)&h2,     g_h2);
    cudaGetSymbolAddress((void**)&neigh2, g_neigh2);
    cudaGetSymbolAddress((void**)&Wt0s,   g_Wt0s);
    cudaGetSymbolAddress((void**)&Wt0n,   g_Wt0n);
    cudaGetSymbolAddress((void**)&Wt1s,   g_Wt1s);
    cudaGetSymbolAddress((void**)&Wt1n,   g_Wt1n);
    cudaGetSymbolAddress((void**)&Wt2s,   g_Wt2s);
    cudaGetSymbolAddress((void**)&Wt2n,   g_Wt2n);

    cudaFuncSetAttribute((const void*)layer0_fused_kernel,
                         cudaFuncAttributeMaxDynamicSharedMemorySize, SMEM_GEMM_BYTES);
    cudaFuncSetAttribute((const void*)sage_mma_gemm_bn64<true>,
                         cudaFuncAttributeMaxDynamicSharedMemorySize, SMEM_B64_BYTES);
    cudaFuncSetAttribute((const void*)sage_mma_gemm<false>,
                         cudaFuncAttributeMaxDynamicSharedMemorySize, SMEM_GEMM_BYTES);

    // #1: transposes + flag clear
    transpose_all_kernel<<<1024, dim3(32, 8)>>>(Ws0, Wt0s, Wn0, Wt0n,
                                                Ws1, Wt1s, Wn1, Wt1n,
                                                Ws2, Wt2s, Wn2, Wt2n);
    // #2: fused layer 0 (104 gather producers + 3872 GEMM consumers)
    layer0_fused_kernel<<<GATHER_CTAS + 4 * NUNITS, 256, SMEM_GEMM_BYTES>>>(
        x, e0, neigh0, xr, Wt0s, Wt0n, b0, h1);
    // #3: gather1 (whole-chip)
    gather_mean_kernel<<<N2_SZ / 4, dim3(H_DIM / 8, 4)>>>(h1, e1, neigh1, H_DIM / 8, N2_SZ);
    // #4: Layer-1 dual GEMM, BN=64 (704 CTAs — better tail)
    sage_mma_gemm_bn64<true><<<dim3(H_DIM / 64, N2_SZ / 128), 256, SMEM_B64_BYTES>>>(
        h1, neigh1, Wt1s, Wt1n, b1, h2, H_DIM, H_DIM);
    // #5: gather2
    gather_mean_kernel<<<SEEDS_SZ / 4, dim3(H_DIM / 8, 4)>>>(h2, e2, neigh2, H_DIM / 8, SEEDS_SZ);
    // #6: Layer-2 dual GEMM (canonical output layout)
    sage_mma_gemm<false><<<dim3(C_DIM / 128, SEEDS_SZ / 128), 256, SMEM_GEMM_BYTES>>>(
        h2, neigh2, Wt2s, Wt2n, b2, out, H_DIM, C_DIM);
}